// round 14
// baseline (speedup 1.0000x reference)
#include <cuda_runtime.h>

#define N    192
#define N4   (N/4)          // 48 float4 per k-row
#define N2F  (N/2)          // 96 float2 per k-row
#define N2   (N*N)
#define N3   (N*N*N)
#define C4   (N3/4)
#define SI4  (N2/4)
#define SI2  (N2/2)         // i-stride in float2 units
#define JC   6              // j-rows marched per thread

#define DT      0.01f
#define HCELL   0.1f
#define GDT     (9.81f * 0.01f)
#define SCALE   (DT / HCELL)
#define ALPHA   (0.01f * 0.01f / (0.1f * 0.1f))
#define INVDIF  (1.0f / (1.0f + 6.0f * ALPHA))
#define INV2H   (1.0f / (2.0f * HCELL))
#define SIXTH   (1.0f / 6.0f)

__device__ float g_velA[3 * N3];
__device__ float g_velB[3 * N3];
__device__ float g_div [N3];
__device__ float g_pA  [N3];
__device__ float g_pB  [N3];

// ============================================================
// helper: k-neighbors across float4 boundary via warp shuffle
// (float4 kernels: div_p0, project)
// ============================================================
__device__ __forceinline__ void knb(const float4* base, int t, int k4,
                                    float cw, float cx,
                                    float& lm, float& rp) {
    lm = __shfl_up_sync(0xffffffffu, cw, 1);
    rp = __shfl_down_sync(0xffffffffu, cx, 1);
    int lane = threadIdx.x & 31;
    const float* s = (const float*)base;
    if (lane == 0  && k4 > 0)      lm = s[4 * t - 1];
    if (lane == 31 && k4 < N4 - 1) rp = s[4 * t + 4];
}

// ============================================================
// 1) gravity + semi-Lagrangian advection (scalar — best measured)
// ============================================================
__global__ void k_advect(const float* __restrict__ vin, float* __restrict__ vout) {
    int idx = blockIdx.x * blockDim.x + threadIdx.x;
    if (idx >= N3) return;
    int k = idx % N;
    int j = (idx / N) % N;
    int i = idx / N2;

    float vx = vin[idx];
    float vy = vin[N3 + idx];
    float vz = vin[2 * N3 + idx] - GDT;

    float px = fminf(fmaxf((float)i - vx * SCALE, 0.0f), (float)(N - 2));
    float py = fminf(fmaxf((float)j - vy * SCALE, 0.0f), (float)(N - 2));
    float pz = fminf(fmaxf((float)k - vz * SCALE, 0.0f), (float)(N - 2));

    int ix = (int)px, iy = (int)py, iz = (int)pz;
    float wx1 = px - (float)ix, wy1 = py - (float)iy, wz1 = pz - (float)iz;
    float wx0 = 1.0f - wx1,     wy0 = 1.0f - wy1,    wz0 = 1.0f - wz1;

    float w000 = wx0 * wy0 * wz0, w001 = wx0 * wy0 * wz1;
    float w010 = wx0 * wy1 * wz0, w011 = wx0 * wy1 * wz1;
    float w100 = wx1 * wy0 * wz0, w101 = wx1 * wy0 * wz1;
    float w110 = wx1 * wy1 * wz0, w111 = wx1 * wy1 * wz1;

    int b = (ix * N + iy) * N + iz;

    #pragma unroll
    for (int c = 0; c < 3; c++) {
        const float* f = vin + c * N3;
        float v = f[b]          * w000 + f[b + 1]          * w001
                + f[b + N]      * w010 + f[b + N + 1]      * w011
                + f[b + N2]     * w100 + f[b + N2 + 1]     * w101
                + f[b + N2 + N] * w110 + f[b + N2 + N + 1] * w111;
        if (c == 2) v -= GDT;
        vout[c * N3 + idx] = v;
    }
}

// ============================================================
// 2) diffusion sweep: register j-marching, 2 i-rows/thread,
//    FLOAT2 k-granularity (2x threads, same traffic), per-component.
// ============================================================
template<bool SKIP>
__global__ void k_diffuseM(const float2* __restrict__ in, float2* __restrict__ out) {
    int g = blockIdx.x * blockDim.x + threadIdx.x;
    int k2   = g % N2F;
    int rest = g / N2F;
    int ipair = rest % (N / 2);
    int jc    = rest / (N / 2);
    int i0 = 2 * ipair, i1 = i0 + 1;
    int j0 = jc * JC;
    int lane = threadIdx.x & 31;

    const float* ps = (const float*)in;
    const float2 Z = make_float2(0.f, 0.f);

    float2 c0m = Z, c1m = Z;
    if (j0 > 0) {
        c0m = in[(i0 * N + j0 - 1) * N2F + k2];
        c1m = in[(i1 * N + j0 - 1) * N2F + k2];
    }
    float2 c0 = in[(i0 * N + j0) * N2F + k2];
    float2 c1 = in[(i1 * N + j0) * N2F + k2];

    bool has_im = (i0 > 0);
    bool has_ip = (i1 < N - 1);

    #pragma unroll
    for (int s = 0; s < JC; s++) {
        int j = j0 + s;
        int t0 = (i0 * N + j) * N2F + k2;
        int t1 = t0 + SI2;

        float2 c0p = Z, c1p = Z;
        if (j + 1 < N) {
            c0p = in[t0 + N2F];
            c1p = in[t1 + N2F];
        }

        float lm0 = __shfl_up_sync(0xffffffffu, c0.y, 1);
        float rp0 = __shfl_down_sync(0xffffffffu, c0.x, 1);
        float lm1 = __shfl_up_sync(0xffffffffu, c1.y, 1);
        float rp1 = __shfl_down_sync(0xffffffffu, c1.x, 1);
        if (lane == 0 && k2 > 0) {
            lm0 = ps[2 * t0 - 1];
            lm1 = ps[2 * t1 - 1];
        }
        if (lane == 31 && k2 < N2F - 1) {
            rp0 = ps[2 * t0 + 2];
            rp1 = ps[2 * t1 + 2];
        }

        if (j != 0 && j != N - 1) {
            if (has_im) {
                float2 im = in[t0 - SI2];
                float2 o0;
                o0.x = (k2 == 0) ? c0.x
                     : (c0.x + ALPHA * (im.x + c1.x + c0m.x + c0p.x + lm0 + c0.y)) * INVDIF;
                o0.y = (k2 == N2F - 1) ? c0.y
                     : (c0.y + ALPHA * (im.y + c1.y + c0m.y + c0p.y + c0.x + rp0)) * INVDIF;
                out[t0] = o0;
            } else if (!SKIP) {
                out[t0] = c0;
            }
            if (has_ip) {
                float2 ip = in[t1 + SI2];
                float2 o1;
                o1.x = (k2 == 0) ? c1.x
                     : (c1.x + ALPHA * (c0.x + ip.x + c1m.x + c1p.x + lm1 + c1.y)) * INVDIF;
                o1.y = (k2 == N2F - 1) ? c1.y
                     : (c1.y + ALPHA * (c0.y + ip.y + c1m.y + c1p.y + c1.x + rp1)) * INVDIF;
                out[t1] = o1;
            } else if (!SKIP) {
                out[t1] = c1;
            }
        } else if (!SKIP) {
            out[t0] = c0;
            out[t1] = c1;
        }

        c0m = c0; c0 = c0p;
        c1m = c1; c1 = c1p;
    }
}

// ============================================================
// 3) divergence + first pressure sweep fused (p1 = div/6), float4
// ============================================================
__global__ void k_div_p0(const float4* __restrict__ v,
                         float4* __restrict__ dv, float4* __restrict__ p) {
    int t = blockIdx.x * blockDim.x + threadIdx.x;
    int k4 = t % N4;
    int j  = (t / N4) % N;
    int i  = t / SI4;

    const float4* vz = v + 2 * C4;
    float4 zc = vz[t];
    float zl, zr;
    knb(vz, t, k4, zc.w, zc.x, zl, zr);

    float4 d = make_float4(0.f, 0.f, 0.f, 0.f);
    if (!(i == 0 || i == N - 1 || j == 0 || j == N - 1)) {
        const float4* vx = v;
        const float4* vy = v + C4;
        float4 xa = vx[t + SI4], xb = vx[t - SI4];
        float4 ya = vy[t + N4],  yb = vy[t - N4];

        if (k4 != 0)
            d.x = ((xa.x - xb.x) + (ya.x - yb.x) + (zc.y - zl))   * INV2H;
        d.y =     ((xa.y - xb.y) + (ya.y - yb.y) + (zc.z - zc.x)) * INV2H;
        d.z =     ((xa.z - xb.z) + (ya.z - yb.z) + (zc.w - zc.y)) * INV2H;
        if (k4 != N4 - 1)
            d.w = ((xa.w - xb.w) + (ya.w - yb.w) + (zr   - zc.z)) * INV2H;
    }
    dv[t] = d;
    p[t] = make_float4(d.x * SIXTH, d.y * SIXTH, d.z * SIXTH, d.w * SIXTH);
}

// ============================================================
// 4) pressure Jacobi sweep: register j-marching, FLOAT2 granularity
// ============================================================
template<bool SKIP>
__global__ void k_pressureM(const float2* __restrict__ dv,
                            const float2* __restrict__ pin,
                            float2* __restrict__ pout) {
    int g = blockIdx.x * blockDim.x + threadIdx.x;
    int k2   = g % N2F;
    int rest = g / N2F;
    int ipair = rest % (N / 2);
    int jc    = rest / (N / 2);
    int i0 = 2 * ipair, i1 = i0 + 1;
    int j0 = jc * JC;
    int lane = threadIdx.x & 31;

    const float* ps = (const float*)pin;
    const float2 Z = make_float2(0.f, 0.f);

    float2 c0m = Z, c1m = Z;
    if (j0 > 0) {
        c0m = pin[(i0 * N + j0 - 1) * N2F + k2];
        c1m = pin[(i1 * N + j0 - 1) * N2F + k2];
    }
    float2 c0 = pin[(i0 * N + j0) * N2F + k2];
    float2 c1 = pin[(i1 * N + j0) * N2F + k2];

    bool has_im = (i0 > 0);
    bool has_ip = (i1 < N - 1);

    #pragma unroll
    for (int s = 0; s < JC; s++) {
        int j = j0 + s;
        int t0 = (i0 * N + j) * N2F + k2;
        int t1 = t0 + SI2;

        float2 c0p = Z, c1p = Z;
        if (j + 1 < N) {
            c0p = pin[t0 + N2F];
            c1p = pin[t1 + N2F];
        }

        float lm0 = __shfl_up_sync(0xffffffffu, c0.y, 1);
        float rp0 = __shfl_down_sync(0xffffffffu, c0.x, 1);
        float lm1 = __shfl_up_sync(0xffffffffu, c1.y, 1);
        float rp1 = __shfl_down_sync(0xffffffffu, c1.x, 1);
        if (lane == 0 && k2 > 0) {
            lm0 = ps[2 * t0 - 1];
            lm1 = ps[2 * t1 - 1];
        }
        if (lane == 31 && k2 < N2F - 1) {
            rp0 = ps[2 * t0 + 2];
            rp1 = ps[2 * t1 + 2];
        }

        if (j != 0 && j != N - 1) {
            if (has_im) {
                float2 im = pin[t0 - SI2];
                float2 d0 = dv[t0];
                float2 o0;
                o0.x = (k2 == 0) ? 0.f
                     : (d0.x + im.x + c1.x + c0m.x + c0p.x + lm0 + c0.y) * SIXTH;
                o0.y = (k2 == N2F - 1) ? 0.f
                     : (d0.y + im.y + c1.y + c0m.y + c0p.y + c0.x + rp0) * SIXTH;
                pout[t0] = o0;
            } else if (!SKIP) {
                pout[t0] = Z;
            }
            if (has_ip) {
                float2 ip = pin[t1 + SI2];
                float2 d1 = dv[t1];
                float2 o1;
                o1.x = (k2 == 0) ? 0.f
                     : (d1.x + c0.x + ip.x + c1m.x + c1p.x + lm1 + c1.y) * SIXTH;
                o1.y = (k2 == N2F - 1) ? 0.f
                     : (d1.y + c0.y + ip.y + c1m.y + c1p.y + c1.x + rp1) * SIXTH;
                pout[t1] = o1;
            } else if (!SKIP) {
                pout[t1] = Z;
            }
        } else if (!SKIP) {
            pout[t0] = Z;
            pout[t1] = Z;
        }

        c0m = c0; c0 = c0p;
        c1m = c1; c1 = c1p;
    }
}

// ============================================================
// 5) subtract pressure gradient -> output (float4)
// ============================================================
__global__ void k_project4(const float4* __restrict__ v,
                           const float4* __restrict__ p,
                           float4* __restrict__ out) {
    int t = blockIdx.x * blockDim.x + threadIdx.x;
    int k4 = t % N4;
    int j  = (t / N4) % N;
    int i  = t / SI4;

    float4 pz = p[t];
    float pl, pr;
    knb(p, t, k4, pz.w, pz.x, pl, pr);

    float4 v0 = v[t], v1 = v[t + C4], v2 = v[t + 2 * C4];

    if (!(i == 0 || i == N - 1 || j == 0 || j == N - 1)) {
        float4 pa = p[t + SI4], pb = p[t - SI4];
        float4 pc = p[t + N4],  pd = p[t - N4];

        if (k4 != 0) {
            v0.x -= (pa.x - pb.x) * INV2H;
            v1.x -= (pc.x - pd.x) * INV2H;
            v2.x -= (pz.y - pl)   * INV2H;
        }
        v0.y -= (pa.y - pb.y) * INV2H;
        v1.y -= (pc.y - pd.y) * INV2H;
        v2.y -= (pz.z - pz.x) * INV2H;

        v0.z -= (pa.z - pb.z) * INV2H;
        v1.z -= (pc.z - pd.z) * INV2H;
        v2.z -= (pz.w - pz.y) * INV2H;

        if (k4 != N4 - 1) {
            v0.w -= (pa.w - pb.w) * INV2H;
            v1.w -= (pc.w - pd.w) * INV2H;
            v2.w -= (pr   - pz.z) * INV2H;
        }
    }
    out[t]          = v0;
    out[t + C4]     = v1;
    out[t + 2 * C4] = v2;
}

// ============================================================
// host launcher (graph-capturable: kernel launches only)
// ============================================================
extern "C" void kernel_launch(void* const* d_in, const int* in_sizes, int n_in,
                              void* d_out, int out_size) {
    const float* vin = (const float*)d_in[0];
    float* out = (float*)d_out;

    float *velA, *velB, *dv, *pA, *pB;
    cudaGetSymbolAddress((void**)&velA, g_velA);
    cudaGetSymbolAddress((void**)&velB, g_velB);
    cudaGetSymbolAddress((void**)&dv,   g_div);
    cudaGetSymbolAddress((void**)&pA,   g_pA);
    cudaGetSymbolAddress((void**)&pB,   g_pB);

    const int T = 256;
    const int blocksCell = (N3 + T - 1) / T;
    const int blocksC4   = C4 / T;                           // exact
    const int threadsF2  = N2F * (N / 2) * (N / JC);         // 294912
    const int blocksF2   = threadsF2 / T;                    // 1152, exact

    // gravity + advect
    k_advect<<<blocksCell, T>>>(vin, velA);

    // 5 diffusion sweeps per component, back-to-back (L2-resident).
    // Sweeps 1-2 write boundaries; sweeps 3-5 skip boundary stores.
    for (int c = 0; c < 3; c++) {
        float* a = velA + c * N3;
        float* b = velB + c * N3;
        for (int s = 0; s < 5; s++) {
            if (s < 2)
                k_diffuseM<false><<<blocksF2, T>>>((const float2*)a, (float2*)b);
            else
                k_diffuseM<true ><<<blocksF2, T>>>((const float2*)a, (float2*)b);
            float* tmp = a; a = b; b = tmp;
        }
    }
    float* vdif = velB;   // 5 sweeps (odd) -> each component ends in velB

    // divergence + first pressure sweep fused (writes pA incl. zero boundaries)
    k_div_p0<<<blocksC4, T>>>((const float4*)vdif, (float4*)dv, (float4*)pA);

    // 19 remaining pressure sweeps: first writes pB boundaries, rest skip
    float* pa = pA; float* pb = pB;
    for (int s = 0; s < 19; s++) {
        if (s == 0)
            k_pressureM<false><<<blocksF2, T>>>((const float2*)dv, (const float2*)pa, (float2*)pb);
        else
            k_pressureM<true ><<<blocksF2, T>>>((const float2*)dv, (const float2*)pa, (float2*)pb);
        float* tmp = pa; pa = pb; pb = tmp;
    }

    // gradient subtract -> output
    k_project4<<<blocksC4, T>>>((const float4*)vdif, (const float4*)pa, (float4*)out);
}

// round 15
// speedup vs baseline: 1.1717x; 1.1717x over previous
#include <cuda_runtime.h>

#define N    192
#define N4   (N/4)          // 48
#define N2   (N*N)
#define N3   (N*N*N)
#define C4   (N3/4)
#define SI4  (N2/4)
#define JC   6              // j-rows marched per thread (proven)

#define DT      0.01f
#define HCELL   0.1f
#define GDT     (9.81f * 0.01f)
#define SCALE   (DT / HCELL)
#define ALPHA   (0.01f * 0.01f / (0.1f * 0.1f))
#define INVDIF  (1.0f / (1.0f + 6.0f * ALPHA))
#define INV2H   (1.0f / (2.0f * HCELL))
#define SIXTH   (1.0f / 6.0f)

__device__ float g_velA[3 * N3];
__device__ float g_velB[3 * N3];
__device__ float g_div [N3];
__device__ float g_pA  [N3];
__device__ float g_pB  [N3];

// ============================================================
// helper: k-neighbors across float4 boundary via warp shuffle.
// ============================================================
__device__ __forceinline__ void knb(const float4* base, int t, int k4,
                                    float cw, float cx,
                                    float& lm, float& rp) {
    lm = __shfl_up_sync(0xffffffffu, cw, 1);
    rp = __shfl_down_sync(0xffffffffu, cx, 1);
    int lane = threadIdx.x & 31;
    const float* s = (const float*)base;
    if (lane == 0  && k4 > 0)      lm = s[4 * t - 1];
    if (lane == 31 && k4 < N4 - 1) rp = s[4 * t + 4];
}

// ============================================================
// 1) gravity + semi-Lagrangian advection (scalar — best measured)
// ============================================================
__global__ void k_advect(const float* __restrict__ vin, float* __restrict__ vout) {
    int idx = blockIdx.x * blockDim.x + threadIdx.x;
    if (idx >= N3) return;
    int k = idx % N;
    int j = (idx / N) % N;
    int i = idx / N2;

    float vx = vin[idx];
    float vy = vin[N3 + idx];
    float vz = vin[2 * N3 + idx] - GDT;

    float px = fminf(fmaxf((float)i - vx * SCALE, 0.0f), (float)(N - 2));
    float py = fminf(fmaxf((float)j - vy * SCALE, 0.0f), (float)(N - 2));
    float pz = fminf(fmaxf((float)k - vz * SCALE, 0.0f), (float)(N - 2));

    int ix = (int)px, iy = (int)py, iz = (int)pz;
    float wx1 = px - (float)ix, wy1 = py - (float)iy, wz1 = pz - (float)iz;
    float wx0 = 1.0f - wx1,     wy0 = 1.0f - wy1,    wz0 = 1.0f - wz1;

    float w000 = wx0 * wy0 * wz0, w001 = wx0 * wy0 * wz1;
    float w010 = wx0 * wy1 * wz0, w011 = wx0 * wy1 * wz1;
    float w100 = wx1 * wy0 * wz0, w101 = wx1 * wy0 * wz1;
    float w110 = wx1 * wy1 * wz0, w111 = wx1 * wy1 * wz1;

    int b = (ix * N + iy) * N + iz;

    #pragma unroll
    for (int c = 0; c < 3; c++) {
        const float* f = vin + c * N3;
        float v = f[b]          * w000 + f[b + 1]          * w001
                + f[b + N]      * w010 + f[b + N + 1]      * w011
                + f[b + N2]     * w100 + f[b + N2 + 1]     * w101
                + f[b + N2 + N] * w110 + f[b + N2 + N + 1] * w111;
        if (c == 2) v -= GDT;
        vout[c * N3 + idx] = v;
    }
}

// ============================================================
// 2) diffusion sweep: register j-marching, 2 i-rows/thread, float4.
//    Component selected by blockIdx.y (pointers point at comp 0;
//    gridDim.y = #components in this launch). SKIP elides the
//    sweep-invariant boundary stores (valid from sweep 3 on).
// ============================================================
template<bool SKIP>
__global__ void k_diffuseM(const float4* __restrict__ inb, float4* __restrict__ outb) {
    const float4* in  = inb  + blockIdx.y * C4;
    float4*       out = outb + blockIdx.y * C4;

    int g = blockIdx.x * blockDim.x + threadIdx.x;
    int k4   = g % N4;
    int rest = g / N4;
    int ipair = rest % (N / 2);
    int jc    = rest / (N / 2);
    int i0 = 2 * ipair, i1 = i0 + 1;
    int j0 = jc * JC;
    int lane = threadIdx.x & 31;

    const float* ps = (const float*)in;
    const float4 Z = make_float4(0.f, 0.f, 0.f, 0.f);

    float4 c0m = Z, c1m = Z;
    if (j0 > 0) {
        c0m = in[(i0 * N + j0 - 1) * N4 + k4];
        c1m = in[(i1 * N + j0 - 1) * N4 + k4];
    }
    float4 c0 = in[(i0 * N + j0) * N4 + k4];
    float4 c1 = in[(i1 * N + j0) * N4 + k4];

    bool has_im = (i0 > 0);
    bool has_ip = (i1 < N - 1);

    #pragma unroll
    for (int s = 0; s < JC; s++) {
        int j = j0 + s;
        int t0 = (i0 * N + j) * N4 + k4;
        int t1 = t0 + SI4;

        float4 c0p = Z, c1p = Z;
        if (j + 1 < N) {
            c0p = in[t0 + N4];
            c1p = in[t1 + N4];
        }

        float lm0 = __shfl_up_sync(0xffffffffu, c0.w, 1);
        float rp0 = __shfl_down_sync(0xffffffffu, c0.x, 1);
        float lm1 = __shfl_up_sync(0xffffffffu, c1.w, 1);
        float rp1 = __shfl_down_sync(0xffffffffu, c1.x, 1);
        if (lane == 0 && k4 > 0) {
            lm0 = ps[4 * t0 - 1];
            lm1 = ps[4 * t1 - 1];
        }
        if (lane == 31 && k4 < N4 - 1) {
            rp0 = ps[4 * t0 + 4];
            rp1 = ps[4 * t1 + 4];
        }

        if (j != 0 && j != N - 1) {
            if (has_im) {
                float4 im = in[t0 - SI4];
                float4 o0;
                o0.x = (k4 == 0) ? c0.x
                     : (c0.x + ALPHA * (im.x + c1.x + c0m.x + c0p.x + lm0 + c0.y)) * INVDIF;
                o0.y =  (c0.y + ALPHA * (im.y + c1.y + c0m.y + c0p.y + c0.x + c0.z)) * INVDIF;
                o0.z =  (c0.z + ALPHA * (im.z + c1.z + c0m.z + c0p.z + c0.y + c0.w)) * INVDIF;
                o0.w = (k4 == N4 - 1) ? c0.w
                     : (c0.w + ALPHA * (im.w + c1.w + c0m.w + c0p.w + c0.z + rp0)) * INVDIF;
                out[t0] = o0;
            } else if (!SKIP) {
                out[t0] = c0;
            }
            if (has_ip) {
                float4 ip = in[t1 + SI4];
                float4 o1;
                o1.x = (k4 == 0) ? c1.x
                     : (c1.x + ALPHA * (c0.x + ip.x + c1m.x + c1p.x + lm1 + c1.y)) * INVDIF;
                o1.y =  (c1.y + ALPHA * (c0.y + ip.y + c1m.y + c1p.y + c1.x + c1.z)) * INVDIF;
                o1.z =  (c1.z + ALPHA * (c0.z + ip.z + c1m.z + c1p.z + c1.y + c1.w)) * INVDIF;
                o1.w = (k4 == N4 - 1) ? c1.w
                     : (c1.w + ALPHA * (c0.w + ip.w + c1m.w + c1p.w + c1.z + rp1)) * INVDIF;
                out[t1] = o1;
            } else if (!SKIP) {
                out[t1] = c1;
            }
        } else if (!SKIP) {
            out[t0] = c0;
            out[t1] = c1;
        }

        c0m = c0; c0 = c0p;
        c1m = c1; c1 = c1p;
    }
}

// ============================================================
// 3) divergence + first pressure sweep fused (p1 = div/6)
// ============================================================
__global__ void k_div_p0(const float4* __restrict__ v,
                         float4* __restrict__ dv, float4* __restrict__ p) {
    int t = blockIdx.x * blockDim.x + threadIdx.x;
    int k4 = t % N4;
    int j  = (t / N4) % N;
    int i  = t / SI4;

    const float4* vz = v + 2 * C4;
    float4 zc = vz[t];
    float zl, zr;
    knb(vz, t, k4, zc.w, zc.x, zl, zr);

    float4 d = make_float4(0.f, 0.f, 0.f, 0.f);
    if (!(i == 0 || i == N - 1 || j == 0 || j == N - 1)) {
        const float4* vx = v;
        const float4* vy = v + C4;
        float4 xa = vx[t + SI4], xb = vx[t - SI4];
        float4 ya = vy[t + N4],  yb = vy[t - N4];

        if (k4 != 0)
            d.x = ((xa.x - xb.x) + (ya.x - yb.x) + (zc.y - zl))   * INV2H;
        d.y =     ((xa.y - xb.y) + (ya.y - yb.y) + (zc.z - zc.x)) * INV2H;
        d.z =     ((xa.z - xb.z) + (ya.z - yb.z) + (zc.w - zc.y)) * INV2H;
        if (k4 != N4 - 1)
            d.w = ((xa.w - xb.w) + (ya.w - yb.w) + (zr   - zc.z)) * INV2H;
    }
    dv[t] = d;
    p[t] = make_float4(d.x * SIXTH, d.y * SIXTH, d.z * SIXTH, d.w * SIXTH);
}

// ============================================================
// 4) pressure Jacobi sweep: register j-marching, float4 (proven)
// ============================================================
template<bool SKIP>
__global__ void k_pressureM(const float4* __restrict__ dv,
                            const float4* __restrict__ pin,
                            float4* __restrict__ pout) {
    int g = blockIdx.x * blockDim.x + threadIdx.x;
    int k4   = g % N4;
    int rest = g / N4;
    int ipair = rest % (N / 2);
    int jc    = rest / (N / 2);
    int i0 = 2 * ipair, i1 = i0 + 1;
    int j0 = jc * JC;
    int lane = threadIdx.x & 31;

    const float* ps = (const float*)pin;
    const float4 Z = make_float4(0.f, 0.f, 0.f, 0.f);

    float4 c0m = Z, c1m = Z;
    if (j0 > 0) {
        c0m = pin[(i0 * N + j0 - 1) * N4 + k4];
        c1m = pin[(i1 * N + j0 - 1) * N4 + k4];
    }
    float4 c0 = pin[(i0 * N + j0) * N4 + k4];
    float4 c1 = pin[(i1 * N + j0) * N4 + k4];

    bool has_im = (i0 > 0);
    bool has_ip = (i1 < N - 1);

    #pragma unroll
    for (int s = 0; s < JC; s++) {
        int j = j0 + s;
        int t0 = (i0 * N + j) * N4 + k4;
        int t1 = t0 + SI4;

        float4 c0p = Z, c1p = Z;
        if (j + 1 < N) {
            c0p = pin[t0 + N4];
            c1p = pin[t1 + N4];
        }

        float lm0 = __shfl_up_sync(0xffffffffu, c0.w, 1);
        float rp0 = __shfl_down_sync(0xffffffffu, c0.x, 1);
        float lm1 = __shfl_up_sync(0xffffffffu, c1.w, 1);
        float rp1 = __shfl_down_sync(0xffffffffu, c1.x, 1);
        if (lane == 0 && k4 > 0) {
            lm0 = ps[4 * t0 - 1];
            lm1 = ps[4 * t1 - 1];
        }
        if (lane == 31 && k4 < N4 - 1) {
            rp0 = ps[4 * t0 + 4];
            rp1 = ps[4 * t1 + 4];
        }

        if (j != 0 && j != N - 1) {
            if (has_im) {
                float4 im = pin[t0 - SI4];
                float4 d0 = dv[t0];
                float4 o0;
                o0.x = (k4 == 0) ? 0.f
                     : (d0.x + im.x + c1.x + c0m.x + c0p.x + lm0 + c0.y) * SIXTH;
                o0.y =  (d0.y + im.y + c1.y + c0m.y + c0p.y + c0.x + c0.z) * SIXTH;
                o0.z =  (d0.z + im.z + c1.z + c0m.z + c0p.z + c0.y + c0.w) * SIXTH;
                o0.w = (k4 == N4 - 1) ? 0.f
                     : (d0.w + im.w + c1.w + c0m.w + c0p.w + c0.z + rp0) * SIXTH;
                pout[t0] = o0;
            } else if (!SKIP) {
                pout[t0] = Z;
            }
            if (has_ip) {
                float4 ip = pin[t1 + SI4];
                float4 d1 = dv[t1];
                float4 o1;
                o1.x = (k4 == 0) ? 0.f
                     : (d1.x + c0.x + ip.x + c1m.x + c1p.x + lm1 + c1.y) * SIXTH;
                o1.y =  (d1.y + c0.y + ip.y + c1m.y + c1p.y + c1.x + c1.z) * SIXTH;
                o1.z =  (d1.z + c0.z + ip.z + c1m.z + c1p.z + c1.y + c1.w) * SIXTH;
                o1.w = (k4 == N4 - 1) ? 0.f
                     : (d1.w + c0.w + ip.w + c1m.w + c1p.w + c1.z + rp1) * SIXTH;
                pout[t1] = o1;
            } else if (!SKIP) {
                pout[t1] = Z;
            }
        } else if (!SKIP) {
            pout[t0] = Z;
            pout[t1] = Z;
        }

        c0m = c0; c0 = c0p;
        c1m = c1; c1 = c1p;
    }
}

// ============================================================
// 5) subtract pressure gradient -> output
// ============================================================
__global__ void k_project4(const float4* __restrict__ v,
                           const float4* __restrict__ p,
                           float4* __restrict__ out) {
    int t = blockIdx.x * blockDim.x + threadIdx.x;
    int k4 = t % N4;
    int j  = (t / N4) % N;
    int i  = t / SI4;

    float4 pz = p[t];
    float pl, pr;
    knb(p, t, k4, pz.w, pz.x, pl, pr);

    float4 v0 = v[t], v1 = v[t + C4], v2 = v[t + 2 * C4];

    if (!(i == 0 || i == N - 1 || j == 0 || j == N - 1)) {
        float4 pa = p[t + SI4], pb = p[t - SI4];
        float4 pc = p[t + N4],  pd = p[t - N4];

        if (k4 != 0) {
            v0.x -= (pa.x - pb.x) * INV2H;
            v1.x -= (pc.x - pd.x) * INV2H;
            v2.x -= (pz.y - pl)   * INV2H;
        }
        v0.y -= (pa.y - pb.y) * INV2H;
        v1.y -= (pc.y - pd.y) * INV2H;
        v2.y -= (pz.z - pz.x) * INV2H;

        v0.z -= (pa.z - pb.z) * INV2H;
        v1.z -= (pc.z - pd.z) * INV2H;
        v2.z -= (pz.w - pz.y) * INV2H;

        if (k4 != N4 - 1) {
            v0.w -= (pa.w - pb.w) * INV2H;
            v1.w -= (pc.w - pd.w) * INV2H;
            v2.w -= (pr   - pz.z) * INV2H;
        }
    }
    out[t]          = v0;
    out[t + C4]     = v1;
    out[t + 2 * C4] = v2;
}

// ============================================================
// host launcher (graph-capturable: kernel launches only)
// ============================================================
extern "C" void kernel_launch(void* const* d_in, const int* in_sizes, int n_in,
                              void* d_out, int out_size) {
    const float* vin = (const float*)d_in[0];
    float* out = (float*)d_out;

    float *velA, *velB, *dv, *pA, *pB;
    cudaGetSymbolAddress((void**)&velA, g_velA);
    cudaGetSymbolAddress((void**)&velB, g_velB);
    cudaGetSymbolAddress((void**)&dv,   g_div);
    cudaGetSymbolAddress((void**)&pA,   g_pA);
    cudaGetSymbolAddress((void**)&pB,   g_pB);

    const int T = 256;
    const int blocksCell = (N3 + T - 1) / T;
    const int blocksC4   = C4 / T;                           // exact
    const int threadsF   = N4 * (N / 2) * (N / JC);          // 147456
    const int blocksF    = threadsF / T;                     // 576, exact

    // gravity + advect
    k_advect<<<blocksCell, T>>>(vin, velA);

    // 5 diffusion sweeps for components 0+1 together (112 MB L2-resident),
    // then 5 sweeps for component 2 (56 MB resident).
    // Sweeps 1-2 write boundaries (fills both ping-pong buffers); 3-5 skip.
    {
        dim3 gPair(blocksF, 2);
        float* a = velA; float* b = velB;
        for (int s = 0; s < 5; s++) {
            if (s < 2)
                k_diffuseM<false><<<gPair, T>>>((const float4*)a, (float4*)b);
            else
                k_diffuseM<true ><<<gPair, T>>>((const float4*)a, (float4*)b);
            float* tmp = a; a = b; b = tmp;
        }
        float* a2 = velA + 2 * N3; float* b2 = velB + 2 * N3;
        for (int s = 0; s < 5; s++) {
            if (s < 2)
                k_diffuseM<false><<<blocksF, T>>>((const float4*)a2, (float4*)b2);
            else
                k_diffuseM<true ><<<blocksF, T>>>((const float4*)a2, (float4*)b2);
            float* tmp = a2; a2 = b2; b2 = tmp;
        }
    }
    float* vdif = velB;   // 5 sweeps (odd) -> all components end in velB

    // divergence + first pressure sweep fused (writes pA incl. zero boundaries)
    k_div_p0<<<blocksC4, T>>>((const float4*)vdif, (float4*)dv, (float4*)pA);

    // 19 remaining pressure sweeps: first writes pB boundaries, rest skip
    float* pa = pA; float* pb = pB;
    for (int s = 0; s < 19; s++) {
        if (s == 0)
            k_pressureM<false><<<blocksF, T>>>((const float4*)dv, (const float4*)pa, (float4*)pb);
        else
            k_pressureM<true ><<<blocksF, T>>>((const float4*)dv, (const float4*)pa, (float4*)pb);
        float* tmp = pa; pa = pb; pb = tmp;
    }

    // gradient subtract -> output
    k_project4<<<blocksC4, T>>>((const float4*)vdif, (const float4*)pa, (float4*)out);
}

// round 16
// speedup vs baseline: 1.1727x; 1.0008x over previous
#include <cuda_runtime.h>

#define N    192
#define N4   (N/4)          // 48
#define N2   (N*N)
#define N3   (N*N*N)
#define C4   (N3/4)
#define SI4  (N2/4)
#define JC   6              // j-rows marched per thread (proven)

#define DT      0.01f
#define HCELL   0.1f
#define GDT     (9.81f * 0.01f)
#define SCALE   (DT / HCELL)
#define ALPHA   (0.01f * 0.01f / (0.1f * 0.1f))
#define INVDIF  (1.0f / (1.0f + 6.0f * ALPHA))
#define INV2H   (1.0f / (2.0f * HCELL))
#define SIXTH   (1.0f / 6.0f)

__device__ float g_velA[3 * N3];
__device__ float g_velB[3 * N3];
__device__ float g_div [N3];
__device__ float g_pA  [N3];
__device__ float g_pB  [N3];

// ============================================================
// helper: k-neighbors across float4 boundary via warp shuffle.
// ============================================================
__device__ __forceinline__ void knb(const float4* base, int t, int k4,
                                    float cw, float cx,
                                    float& lm, float& rp) {
    lm = __shfl_up_sync(0xffffffffu, cw, 1);
    rp = __shfl_down_sync(0xffffffffu, cx, 1);
    int lane = threadIdx.x & 31;
    const float* s = (const float*)base;
    if (lane == 0  && k4 > 0)      lm = s[4 * t - 1];
    if (lane == 31 && k4 < N4 - 1) rp = s[4 * t + 4];
}

// ============================================================
// 1) gravity + semi-Lagrangian advection (scalar — best measured)
// ============================================================
__global__ void k_advect(const float* __restrict__ vin, float* __restrict__ vout) {
    int idx = blockIdx.x * blockDim.x + threadIdx.x;
    if (idx >= N3) return;
    int k = idx % N;
    int j = (idx / N) % N;
    int i = idx / N2;

    float vx = vin[idx];
    float vy = vin[N3 + idx];
    float vz = vin[2 * N3 + idx] - GDT;

    float px = fminf(fmaxf((float)i - vx * SCALE, 0.0f), (float)(N - 2));
    float py = fminf(fmaxf((float)j - vy * SCALE, 0.0f), (float)(N - 2));
    float pz = fminf(fmaxf((float)k - vz * SCALE, 0.0f), (float)(N - 2));

    int ix = (int)px, iy = (int)py, iz = (int)pz;
    float wx1 = px - (float)ix, wy1 = py - (float)iy, wz1 = pz - (float)iz;
    float wx0 = 1.0f - wx1,     wy0 = 1.0f - wy1,    wz0 = 1.0f - wz1;

    float w000 = wx0 * wy0 * wz0, w001 = wx0 * wy0 * wz1;
    float w010 = wx0 * wy1 * wz0, w011 = wx0 * wy1 * wz1;
    float w100 = wx1 * wy0 * wz0, w101 = wx1 * wy0 * wz1;
    float w110 = wx1 * wy1 * wz0, w111 = wx1 * wy1 * wz1;

    int b = (ix * N + iy) * N + iz;

    #pragma unroll
    for (int c = 0; c < 3; c++) {
        const float* f = vin + c * N3;
        float v = f[b]          * w000 + f[b + 1]          * w001
                + f[b + N]      * w010 + f[b + N + 1]      * w011
                + f[b + N2]     * w100 + f[b + N2 + 1]     * w101
                + f[b + N2 + N] * w110 + f[b + N2 + N + 1] * w111;
        if (c == 2) v -= GDT;
        vout[c * N3 + idx] = v;
    }
}

// ============================================================
// 2) diffusion sweep: register j-marching, 4 i-rows/thread (quad),
//    per-component launch (L2-resident). Rows 1,2 get both
//    i-neighbors from registers. SKIP elides boundary stores.
// ============================================================
template<bool SKIP>
__global__ void k_diffuseQ(const float4* __restrict__ in, float4* __restrict__ out) {
    int g = blockIdx.x * blockDim.x + threadIdx.x;
    int k4   = g % N4;
    int rest = g / N4;
    int iq   = rest % (N / 4);
    int jc   = rest / (N / 4);
    int i0 = 4 * iq;
    int j0 = jc * JC;
    int lane = threadIdx.x & 31;

    const float* ps = (const float*)in;
    const float4 Z = make_float4(0.f, 0.f, 0.f, 0.f);

    float4 cm[4], c[4];
    #pragma unroll
    for (int r = 0; r < 4; r++) {
        cm[r] = Z;
        if (j0 > 0) cm[r] = in[((i0 + r) * N + j0 - 1) * N4 + k4];
        c[r] = in[((i0 + r) * N + j0) * N4 + k4];
    }
    bool has_im = (i0 > 0);
    bool has_ip = (i0 + 4 < N);

    #pragma unroll
    for (int s = 0; s < JC; s++) {
        int j = j0 + s;
        int tb = (i0 * N + j) * N4 + k4;   // row r index: tb + r*SI4

        float4 cp[4];
        #pragma unroll
        for (int r = 0; r < 4; r++) {
            cp[r] = Z;
            if (j + 1 < N) cp[r] = in[tb + r * SI4 + N4];
        }

        float lm[4], rp[4];
        #pragma unroll
        for (int r = 0; r < 4; r++) {
            lm[r] = __shfl_up_sync(0xffffffffu, c[r].w, 1);
            rp[r] = __shfl_down_sync(0xffffffffu, c[r].x, 1);
        }
        if (lane == 0 && k4 > 0) {
            #pragma unroll
            for (int r = 0; r < 4; r++) lm[r] = ps[4 * (tb + r * SI4) - 1];
        }
        if (lane == 31 && k4 < N4 - 1) {
            #pragma unroll
            for (int r = 0; r < 4; r++) rp[r] = ps[4 * (tb + r * SI4) + 4];
        }

        if (j != 0 && j != N - 1) {
            float4 im = has_im ? in[tb - SI4]     : Z;
            float4 ip = has_ip ? in[tb + 4 * SI4] : Z;
            #pragma unroll
            for (int r = 0; r < 4; r++) {
                bool comp = (r == 0) ? has_im : (r == 3) ? has_ip : true;
                if (comp) {
                    float4 bl = (r == 0) ? im : c[r - 1];
                    float4 ab = (r == 3) ? ip : c[r + 1];
                    float4 o;
                    o.x = (k4 == 0) ? c[r].x
                        : (c[r].x + ALPHA * (bl.x + ab.x + cm[r].x + cp[r].x + lm[r]  + c[r].y)) * INVDIF;
                    o.y =  (c[r].y + ALPHA * (bl.y + ab.y + cm[r].y + cp[r].y + c[r].x + c[r].z)) * INVDIF;
                    o.z =  (c[r].z + ALPHA * (bl.z + ab.z + cm[r].z + cp[r].z + c[r].y + c[r].w)) * INVDIF;
                    o.w = (k4 == N4 - 1) ? c[r].w
                        : (c[r].w + ALPHA * (bl.w + ab.w + cm[r].w + cp[r].w + c[r].z + rp[r])) * INVDIF;
                    out[tb + r * SI4] = o;
                } else if (!SKIP) {
                    out[tb + r * SI4] = c[r];
                }
            }
        } else if (!SKIP) {
            #pragma unroll
            for (int r = 0; r < 4; r++) out[tb + r * SI4] = c[r];
        }

        #pragma unroll
        for (int r = 0; r < 4; r++) { cm[r] = c[r]; c[r] = cp[r]; }
    }
}

// ============================================================
// 3) divergence + first pressure sweep fused (p1 = div/6)
// ============================================================
__global__ void k_div_p0(const float4* __restrict__ v,
                         float4* __restrict__ dv, float4* __restrict__ p) {
    int t = blockIdx.x * blockDim.x + threadIdx.x;
    int k4 = t % N4;
    int j  = (t / N4) % N;
    int i  = t / SI4;

    const float4* vz = v + 2 * C4;
    float4 zc = vz[t];
    float zl, zr;
    knb(vz, t, k4, zc.w, zc.x, zl, zr);

    float4 d = make_float4(0.f, 0.f, 0.f, 0.f);
    if (!(i == 0 || i == N - 1 || j == 0 || j == N - 1)) {
        const float4* vx = v;
        const float4* vy = v + C4;
        float4 xa = vx[t + SI4], xb = vx[t - SI4];
        float4 ya = vy[t + N4],  yb = vy[t - N4];

        if (k4 != 0)
            d.x = ((xa.x - xb.x) + (ya.x - yb.x) + (zc.y - zl))   * INV2H;
        d.y =     ((xa.y - xb.y) + (ya.y - yb.y) + (zc.z - zc.x)) * INV2H;
        d.z =     ((xa.z - xb.z) + (ya.z - yb.z) + (zc.w - zc.y)) * INV2H;
        if (k4 != N4 - 1)
            d.w = ((xa.w - xb.w) + (ya.w - yb.w) + (zr   - zc.z)) * INV2H;
    }
    dv[t] = d;
    p[t] = make_float4(d.x * SIXTH, d.y * SIXTH, d.z * SIXTH, d.w * SIXTH);
}

// ============================================================
// 4) pressure Jacobi sweep: register j-marching, 4 i-rows/thread
// ============================================================
template<bool SKIP>
__global__ void k_pressureQ(const float4* __restrict__ dv,
                            const float4* __restrict__ pin,
                            float4* __restrict__ pout) {
    int g = blockIdx.x * blockDim.x + threadIdx.x;
    int k4   = g % N4;
    int rest = g / N4;
    int iq   = rest % (N / 4);
    int jc   = rest / (N / 4);
    int i0 = 4 * iq;
    int j0 = jc * JC;
    int lane = threadIdx.x & 31;

    const float* ps = (const float*)pin;
    const float4 Z = make_float4(0.f, 0.f, 0.f, 0.f);

    float4 cm[4], c[4];
    #pragma unroll
    for (int r = 0; r < 4; r++) {
        cm[r] = Z;
        if (j0 > 0) cm[r] = pin[((i0 + r) * N + j0 - 1) * N4 + k4];
        c[r] = pin[((i0 + r) * N + j0) * N4 + k4];
    }
    bool has_im = (i0 > 0);
    bool has_ip = (i0 + 4 < N);

    #pragma unroll
    for (int s = 0; s < JC; s++) {
        int j = j0 + s;
        int tb = (i0 * N + j) * N4 + k4;

        float4 cp[4];
        #pragma unroll
        for (int r = 0; r < 4; r++) {
            cp[r] = Z;
            if (j + 1 < N) cp[r] = pin[tb + r * SI4 + N4];
        }

        float lm[4], rp[4];
        #pragma unroll
        for (int r = 0; r < 4; r++) {
            lm[r] = __shfl_up_sync(0xffffffffu, c[r].w, 1);
            rp[r] = __shfl_down_sync(0xffffffffu, c[r].x, 1);
        }
        if (lane == 0 && k4 > 0) {
            #pragma unroll
            for (int r = 0; r < 4; r++) lm[r] = ps[4 * (tb + r * SI4) - 1];
        }
        if (lane == 31 && k4 < N4 - 1) {
            #pragma unroll
            for (int r = 0; r < 4; r++) rp[r] = ps[4 * (tb + r * SI4) + 4];
        }

        if (j != 0 && j != N - 1) {
            float4 im = has_im ? pin[tb - SI4]     : Z;
            float4 ip = has_ip ? pin[tb + 4 * SI4] : Z;
            #pragma unroll
            for (int r = 0; r < 4; r++) {
                bool comp = (r == 0) ? has_im : (r == 3) ? has_ip : true;
                if (comp) {
                    float4 bl = (r == 0) ? im : c[r - 1];
                    float4 ab = (r == 3) ? ip : c[r + 1];
                    float4 d  = dv[tb + r * SI4];
                    float4 o;
                    o.x = (k4 == 0) ? 0.f
                        : (d.x + bl.x + ab.x + cm[r].x + cp[r].x + lm[r]  + c[r].y) * SIXTH;
                    o.y =  (d.y + bl.y + ab.y + cm[r].y + cp[r].y + c[r].x + c[r].z) * SIXTH;
                    o.z =  (d.z + bl.z + ab.z + cm[r].z + cp[r].z + c[r].y + c[r].w) * SIXTH;
                    o.w = (k4 == N4 - 1) ? 0.f
                        : (d.w + bl.w + ab.w + cm[r].w + cp[r].w + c[r].z + rp[r]) * SIXTH;
                    pout[tb + r * SI4] = o;
                } else if (!SKIP) {
                    pout[tb + r * SI4] = Z;
                }
            }
        } else if (!SKIP) {
            #pragma unroll
            for (int r = 0; r < 4; r++) pout[tb + r * SI4] = Z;
        }

        #pragma unroll
        for (int r = 0; r < 4; r++) { cm[r] = c[r]; c[r] = cp[r]; }
    }
}

// ============================================================
// 5) subtract pressure gradient -> output
// ============================================================
__global__ void k_project4(const float4* __restrict__ v,
                           const float4* __restrict__ p,
                           float4* __restrict__ out) {
    int t = blockIdx.x * blockDim.x + threadIdx.x;
    int k4 = t % N4;
    int j  = (t / N4) % N;
    int i  = t / SI4;

    float4 pz = p[t];
    float pl, pr;
    knb(p, t, k4, pz.w, pz.x, pl, pr);

    float4 v0 = v[t], v1 = v[t + C4], v2 = v[t + 2 * C4];

    if (!(i == 0 || i == N - 1 || j == 0 || j == N - 1)) {
        float4 pa = p[t + SI4], pb = p[t - SI4];
        float4 pc = p[t + N4],  pd = p[t - N4];

        if (k4 != 0) {
            v0.x -= (pa.x - pb.x) * INV2H;
            v1.x -= (pc.x - pd.x) * INV2H;
            v2.x -= (pz.y - pl)   * INV2H;
        }
        v0.y -= (pa.y - pb.y) * INV2H;
        v1.y -= (pc.y - pd.y) * INV2H;
        v2.y -= (pz.z - pz.x) * INV2H;

        v0.z -= (pa.z - pb.z) * INV2H;
        v1.z -= (pc.z - pd.z) * INV2H;
        v2.z -= (pz.w - pz.y) * INV2H;

        if (k4 != N4 - 1) {
            v0.w -= (pa.w - pb.w) * INV2H;
            v1.w -= (pc.w - pd.w) * INV2H;
            v2.w -= (pr   - pz.z) * INV2H;
        }
    }
    out[t]          = v0;
    out[t + C4]     = v1;
    out[t + 2 * C4] = v2;
}

// ============================================================
// host launcher (graph-capturable: kernel launches only)
// ============================================================
extern "C" void kernel_launch(void* const* d_in, const int* in_sizes, int n_in,
                              void* d_out, int out_size) {
    const float* vin = (const float*)d_in[0];
    float* out = (float*)d_out;

    float *velA, *velB, *dv, *pA, *pB;
    cudaGetSymbolAddress((void**)&velA, g_velA);
    cudaGetSymbolAddress((void**)&velB, g_velB);
    cudaGetSymbolAddress((void**)&dv,   g_div);
    cudaGetSymbolAddress((void**)&pA,   g_pA);
    cudaGetSymbolAddress((void**)&pB,   g_pB);

    const int T = 256;
    const int blocksCell = (N3 + T - 1) / T;
    const int blocksC4   = C4 / T;                           // exact
    const int threadsQ   = N4 * (N / 4) * (N / JC);          // 73728
    const int blocksQ    = threadsQ / T;                     // 288, exact

    // gravity + advect
    k_advect<<<blocksCell, T>>>(vin, velA);

    // 5 diffusion sweeps per component, back-to-back (L2-resident).
    // Sweeps 1-2 write boundaries; 3-5 skip boundary stores.
    for (int c = 0; c < 3; c++) {
        float* a = velA + c * N3;
        float* b = velB + c * N3;
        for (int s = 0; s < 5; s++) {
            if (s < 2)
                k_diffuseQ<false><<<blocksQ, T>>>((const float4*)a, (float4*)b);
            else
                k_diffuseQ<true ><<<blocksQ, T>>>((const float4*)a, (float4*)b);
            float* tmp = a; a = b; b = tmp;
        }
    }
    float* vdif = velB;   // 5 sweeps (odd) -> all components end in velB

    // divergence + first pressure sweep fused (writes pA incl. zero boundaries)
    k_div_p0<<<blocksC4, T>>>((const float4*)vdif, (float4*)dv, (float4*)pA);

    // 19 remaining pressure sweeps: first writes pB boundaries, rest skip
    float* pa = pA; float* pb = pB;
    for (int s = 0; s < 19; s++) {
        if (s == 0)
            k_pressureQ<false><<<blocksQ, T>>>((const float4*)dv, (const float4*)pa, (float4*)pb);
        else
            k_pressureQ<true ><<<blocksQ, T>>>((const float4*)dv, (const float4*)pa, (float4*)pb);
        float* tmp = pa; pa = pb; pb = tmp;
    }

    // gradient subtract -> output
    k_project4<<<blocksC4, T>>>((const float4*)vdif, (const float4*)pa, (float4*)out);
}

// round 17
// speedup vs baseline: 1.2350x; 1.0532x over previous
#include <cuda_runtime.h>

#define N    192
#define N4   (N/4)          // 48
#define N2   (N*N)
#define N3   (N*N*N)
#define C4   (N3/4)
#define SI4  (N2/4)
#define JC   6              // j-rows marched per thread (proven)

#define DT      0.01f
#define HCELL   0.1f
#define GDT     (9.81f * 0.01f)
#define SCALE   (DT / HCELL)
#define ALPHA   (0.01f * 0.01f / (0.1f * 0.1f))
#define INVDIF  (1.0f / (1.0f + 6.0f * ALPHA))
#define INV2H   (1.0f / (2.0f * HCELL))
#define SIXTH   (1.0f / 6.0f)

__device__ float g_velA[3 * N3];
__device__ float g_velB[3 * N3];
__device__ float g_div [N3];
__device__ float g_pA  [N3];
__device__ float g_pB  [N3];

// ============================================================
// helper: k-neighbors across float4 boundary via warp shuffle.
// ============================================================
__device__ __forceinline__ void knb(const float4* base, int t, int k4,
                                    float cw, float cx,
                                    float& lm, float& rp) {
    lm = __shfl_up_sync(0xffffffffu, cw, 1);
    rp = __shfl_down_sync(0xffffffffu, cx, 1);
    int lane = threadIdx.x & 31;
    const float* s = (const float*)base;
    if (lane == 0  && k4 > 0)      lm = s[4 * t - 1];
    if (lane == 31 && k4 < N4 - 1) rp = s[4 * t + 4];
}

// ============================================================
// 1) gravity + semi-Lagrangian advection (scalar — best measured)
// ============================================================
__global__ void k_advect(const float* __restrict__ vin, float* __restrict__ vout) {
    int idx = blockIdx.x * blockDim.x + threadIdx.x;
    if (idx >= N3) return;
    int k = idx % N;
    int j = (idx / N) % N;
    int i = idx / N2;

    float vx = vin[idx];
    float vy = vin[N3 + idx];
    float vz = vin[2 * N3 + idx] - GDT;

    float px = fminf(fmaxf((float)i - vx * SCALE, 0.0f), (float)(N - 2));
    float py = fminf(fmaxf((float)j - vy * SCALE, 0.0f), (float)(N - 2));
    float pz = fminf(fmaxf((float)k - vz * SCALE, 0.0f), (float)(N - 2));

    int ix = (int)px, iy = (int)py, iz = (int)pz;
    float wx1 = px - (float)ix, wy1 = py - (float)iy, wz1 = pz - (float)iz;
    float wx0 = 1.0f - wx1,     wy0 = 1.0f - wy1,    wz0 = 1.0f - wz1;

    float w000 = wx0 * wy0 * wz0, w001 = wx0 * wy0 * wz1;
    float w010 = wx0 * wy1 * wz0, w011 = wx0 * wy1 * wz1;
    float w100 = wx1 * wy0 * wz0, w101 = wx1 * wy0 * wz1;
    float w110 = wx1 * wy1 * wz0, w111 = wx1 * wy1 * wz1;

    int b = (ix * N + iy) * N + iz;

    #pragma unroll
    for (int c = 0; c < 3; c++) {
        const float* f = vin + c * N3;
        float v = f[b]          * w000 + f[b + 1]          * w001
                + f[b + N]      * w010 + f[b + N + 1]      * w011
                + f[b + N2]     * w100 + f[b + N2 + 1]     * w101
                + f[b + N2 + N] * w110 + f[b + N2 + N + 1] * w111;
        if (c == 2) v -= GDT;
        vout[c * N3 + idx] = v;
    }
}

// ============================================================
// 2) diffusion sweep: register j-marching, 4 i-rows/thread (quad),
//    per-component launch (L2-resident) — R16 measured winner.
// ============================================================
template<bool SKIP>
__global__ void k_diffuseQ(const float4* __restrict__ in, float4* __restrict__ out) {
    int g = blockIdx.x * blockDim.x + threadIdx.x;
    int k4   = g % N4;
    int rest = g / N4;
    int iq   = rest % (N / 4);
    int jc   = rest / (N / 4);
    int i0 = 4 * iq;
    int j0 = jc * JC;
    int lane = threadIdx.x & 31;

    const float* ps = (const float*)in;
    const float4 Z = make_float4(0.f, 0.f, 0.f, 0.f);

    float4 cm[4], c[4];
    #pragma unroll
    for (int r = 0; r < 4; r++) {
        cm[r] = Z;
        if (j0 > 0) cm[r] = in[((i0 + r) * N + j0 - 1) * N4 + k4];
        c[r] = in[((i0 + r) * N + j0) * N4 + k4];
    }
    bool has_im = (i0 > 0);
    bool has_ip = (i0 + 4 < N);

    #pragma unroll
    for (int s = 0; s < JC; s++) {
        int j = j0 + s;
        int tb = (i0 * N + j) * N4 + k4;

        float4 cp[4];
        #pragma unroll
        for (int r = 0; r < 4; r++) {
            cp[r] = Z;
            if (j + 1 < N) cp[r] = in[tb + r * SI4 + N4];
        }

        float lm[4], rp[4];
        #pragma unroll
        for (int r = 0; r < 4; r++) {
            lm[r] = __shfl_up_sync(0xffffffffu, c[r].w, 1);
            rp[r] = __shfl_down_sync(0xffffffffu, c[r].x, 1);
        }
        if (lane == 0 && k4 > 0) {
            #pragma unroll
            for (int r = 0; r < 4; r++) lm[r] = ps[4 * (tb + r * SI4) - 1];
        }
        if (lane == 31 && k4 < N4 - 1) {
            #pragma unroll
            for (int r = 0; r < 4; r++) rp[r] = ps[4 * (tb + r * SI4) + 4];
        }

        if (j != 0 && j != N - 1) {
            float4 im = has_im ? in[tb - SI4]     : Z;
            float4 ip = has_ip ? in[tb + 4 * SI4] : Z;
            #pragma unroll
            for (int r = 0; r < 4; r++) {
                bool comp = (r == 0) ? has_im : (r == 3) ? has_ip : true;
                if (comp) {
                    float4 bl = (r == 0) ? im : c[r - 1];
                    float4 ab = (r == 3) ? ip : c[r + 1];
                    float4 o;
                    o.x = (k4 == 0) ? c[r].x
                        : (c[r].x + ALPHA * (bl.x + ab.x + cm[r].x + cp[r].x + lm[r]  + c[r].y)) * INVDIF;
                    o.y =  (c[r].y + ALPHA * (bl.y + ab.y + cm[r].y + cp[r].y + c[r].x + c[r].z)) * INVDIF;
                    o.z =  (c[r].z + ALPHA * (bl.z + ab.z + cm[r].z + cp[r].z + c[r].y + c[r].w)) * INVDIF;
                    o.w = (k4 == N4 - 1) ? c[r].w
                        : (c[r].w + ALPHA * (bl.w + ab.w + cm[r].w + cp[r].w + c[r].z + rp[r])) * INVDIF;
                    out[tb + r * SI4] = o;
                } else if (!SKIP) {
                    out[tb + r * SI4] = c[r];
                }
            }
        } else if (!SKIP) {
            #pragma unroll
            for (int r = 0; r < 4; r++) out[tb + r * SI4] = c[r];
        }

        #pragma unroll
        for (int r = 0; r < 4; r++) { cm[r] = c[r]; c[r] = cp[r]; }
    }
}

// ============================================================
// 3) divergence + first pressure sweep fused (p1 = div/6)
// ============================================================
__global__ void k_div_p0(const float4* __restrict__ v,
                         float4* __restrict__ dv, float4* __restrict__ p) {
    int t = blockIdx.x * blockDim.x + threadIdx.x;
    int k4 = t % N4;
    int j  = (t / N4) % N;
    int i  = t / SI4;

    const float4* vz = v + 2 * C4;
    float4 zc = vz[t];
    float zl, zr;
    knb(vz, t, k4, zc.w, zc.x, zl, zr);

    float4 d = make_float4(0.f, 0.f, 0.f, 0.f);
    if (!(i == 0 || i == N - 1 || j == 0 || j == N - 1)) {
        const float4* vx = v;
        const float4* vy = v + C4;
        float4 xa = vx[t + SI4], xb = vx[t - SI4];
        float4 ya = vy[t + N4],  yb = vy[t - N4];

        if (k4 != 0)
            d.x = ((xa.x - xb.x) + (ya.x - yb.x) + (zc.y - zl))   * INV2H;
        d.y =     ((xa.y - xb.y) + (ya.y - yb.y) + (zc.z - zc.x)) * INV2H;
        d.z =     ((xa.z - xb.z) + (ya.z - yb.z) + (zc.w - zc.y)) * INV2H;
        if (k4 != N4 - 1)
            d.w = ((xa.w - xb.w) + (ya.w - yb.w) + (zr   - zc.z)) * INV2H;
    }
    dv[t] = d;
    p[t] = make_float4(d.x * SIXTH, d.y * SIXTH, d.z * SIXTH, d.w * SIXTH);
}

// ============================================================
// 4) pressure Jacobi sweep: register j-marching, 2 i-rows/thread
//    (R13 measured winner)
// ============================================================
template<bool SKIP>
__global__ void k_pressureM(const float4* __restrict__ dv,
                            const float4* __restrict__ pin,
                            float4* __restrict__ pout) {
    int g = blockIdx.x * blockDim.x + threadIdx.x;
    int k4   = g % N4;
    int rest = g / N4;
    int ipair = rest % (N / 2);
    int jc    = rest / (N / 2);
    int i0 = 2 * ipair, i1 = i0 + 1;
    int j0 = jc * JC;
    int lane = threadIdx.x & 31;

    const float* ps = (const float*)pin;
    const float4 Z = make_float4(0.f, 0.f, 0.f, 0.f);

    float4 c0m = Z, c1m = Z;
    if (j0 > 0) {
        c0m = pin[(i0 * N + j0 - 1) * N4 + k4];
        c1m = pin[(i1 * N + j0 - 1) * N4 + k4];
    }
    float4 c0 = pin[(i0 * N + j0) * N4 + k4];
    float4 c1 = pin[(i1 * N + j0) * N4 + k4];

    bool has_im = (i0 > 0);
    bool has_ip = (i1 < N - 1);

    #pragma unroll
    for (int s = 0; s < JC; s++) {
        int j = j0 + s;
        int t0 = (i0 * N + j) * N4 + k4;
        int t1 = t0 + SI4;

        float4 c0p = Z, c1p = Z;
        if (j + 1 < N) {
            c0p = pin[t0 + N4];
            c1p = pin[t1 + N4];
        }

        float lm0 = __shfl_up_sync(0xffffffffu, c0.w, 1);
        float rp0 = __shfl_down_sync(0xffffffffu, c0.x, 1);
        float lm1 = __shfl_up_sync(0xffffffffu, c1.w, 1);
        float rp1 = __shfl_down_sync(0xffffffffu, c1.x, 1);
        if (lane == 0 && k4 > 0) {
            lm0 = ps[4 * t0 - 1];
            lm1 = ps[4 * t1 - 1];
        }
        if (lane == 31 && k4 < N4 - 1) {
            rp0 = ps[4 * t0 + 4];
            rp1 = ps[4 * t1 + 4];
        }

        if (j != 0 && j != N - 1) {
            if (has_im) {
                float4 im = pin[t0 - SI4];
                float4 d0 = dv[t0];
                float4 o0;
                o0.x = (k4 == 0) ? 0.f
                     : (d0.x + im.x + c1.x + c0m.x + c0p.x + lm0 + c0.y) * SIXTH;
                o0.y =  (d0.y + im.y + c1.y + c0m.y + c0p.y + c0.x + c0.z) * SIXTH;
                o0.z =  (d0.z + im.z + c1.z + c0m.z + c0p.z + c0.y + c0.w) * SIXTH;
                o0.w = (k4 == N4 - 1) ? 0.f
                     : (d0.w + im.w + c1.w + c0m.w + c0p.w + c0.z + rp0) * SIXTH;
                pout[t0] = o0;
            } else if (!SKIP) {
                pout[t0] = Z;
            }
            if (has_ip) {
                float4 ip = pin[t1 + SI4];
                float4 d1 = dv[t1];
                float4 o1;
                o1.x = (k4 == 0) ? 0.f
                     : (d1.x + c0.x + ip.x + c1m.x + c1p.x + lm1 + c1.y) * SIXTH;
                o1.y =  (d1.y + c0.y + ip.y + c1m.y + c1p.y + c1.x + c1.z) * SIXTH;
                o1.z =  (d1.z + c0.z + ip.z + c1m.z + c1p.z + c1.y + c1.w) * SIXTH;
                o1.w = (k4 == N4 - 1) ? 0.f
                     : (d1.w + c0.w + ip.w + c1m.w + c1p.w + c1.z + rp1) * SIXTH;
                pout[t1] = o1;
            } else if (!SKIP) {
                pout[t1] = Z;
            }
        } else if (!SKIP) {
            pout[t0] = Z;
            pout[t1] = Z;
        }

        c0m = c0; c0 = c0p;
        c1m = c1; c1 = c1p;
    }
}

// ============================================================
// 5) subtract pressure gradient -> output
// ============================================================
__global__ void k_project4(const float4* __restrict__ v,
                           const float4* __restrict__ p,
                           float4* __restrict__ out) {
    int t = blockIdx.x * blockDim.x + threadIdx.x;
    int k4 = t % N4;
    int j  = (t / N4) % N;
    int i  = t / SI4;

    float4 pz = p[t];
    float pl, pr;
    knb(p, t, k4, pz.w, pz.x, pl, pr);

    float4 v0 = v[t], v1 = v[t + C4], v2 = v[t + 2 * C4];

    if (!(i == 0 || i == N - 1 || j == 0 || j == N - 1)) {
        float4 pa = p[t + SI4], pb = p[t - SI4];
        float4 pc = p[t + N4],  pd = p[t - N4];

        if (k4 != 0) {
            v0.x -= (pa.x - pb.x) * INV2H;
            v1.x -= (pc.x - pd.x) * INV2H;
            v2.x -= (pz.y - pl)   * INV2H;
        }
        v0.y -= (pa.y - pb.y) * INV2H;
        v1.y -= (pc.y - pd.y) * INV2H;
        v2.y -= (pz.z - pz.x) * INV2H;

        v0.z -= (pa.z - pb.z) * INV2H;
        v1.z -= (pc.z - pd.z) * INV2H;
        v2.z -= (pz.w - pz.y) * INV2H;

        if (k4 != N4 - 1) {
            v0.w -= (pa.w - pb.w) * INV2H;
            v1.w -= (pc.w - pd.w) * INV2H;
            v2.w -= (pr   - pz.z) * INV2H;
        }
    }
    out[t]          = v0;
    out[t + C4]     = v1;
    out[t + 2 * C4] = v2;
}

// ============================================================
// host launcher (graph-capturable: kernel launches only)
// ============================================================
extern "C" void kernel_launch(void* const* d_in, const int* in_sizes, int n_in,
                              void* d_out, int out_size) {
    const float* vin = (const float*)d_in[0];
    float* out = (float*)d_out;

    float *velA, *velB, *dv, *pA, *pB;
    cudaGetSymbolAddress((void**)&velA, g_velA);
    cudaGetSymbolAddress((void**)&velB, g_velB);
    cudaGetSymbolAddress((void**)&dv,   g_div);
    cudaGetSymbolAddress((void**)&pA,   g_pA);
    cudaGetSymbolAddress((void**)&pB,   g_pB);

    const int T = 256;
    const int blocksCell = (N3 + T - 1) / T;
    const int blocksC4   = C4 / T;                           // exact
    const int threadsQ   = N4 * (N / 4) * (N / JC);          // 73728
    const int blocksQ    = threadsQ / T;                     // 288, exact
    const int threadsP   = N4 * (N / 2) * (N / JC);          // 147456
    const int blocksP    = threadsP / T;                     // 576, exact

    // gravity + advect
    k_advect<<<blocksCell, T>>>(vin, velA);

    // 5 diffusion sweeps per component, back-to-back (L2-resident, quad).
    // Sweeps 1-2 write boundaries; 3-5 skip boundary stores.
    for (int c = 0; c < 3; c++) {
        float* a = velA + c * N3;
        float* b = velB + c * N3;
        for (int s = 0; s < 5; s++) {
            if (s < 2)
                k_diffuseQ<false><<<blocksQ, T>>>((const float4*)a, (float4*)b);
            else
                k_diffuseQ<true ><<<blocksQ, T>>>((const float4*)a, (float4*)b);
            float* tmp = a; a = b; b = tmp;
        }
    }
    float* vdif = velB;   // 5 sweeps (odd) -> all components end in velB

    // divergence + first pressure sweep fused (writes pA incl. zero boundaries)
    k_div_p0<<<blocksC4, T>>>((const float4*)vdif, (float4*)dv, (float4*)pA);

    // 19 remaining pressure sweeps (pair kernel): first writes pB boundaries, rest skip
    float* pa = pA; float* pb = pB;
    for (int s = 0; s < 19; s++) {
        if (s == 0)
            k_pressureM<false><<<blocksP, T>>>((const float4*)dv, (const float4*)pa, (float4*)pb);
        else
            k_pressureM<true ><<<blocksP, T>>>((const float4*)dv, (const float4*)pa, (float4*)pb);
        float* tmp = pa; pa = pb; pb = tmp;
    }

    // gradient subtract -> output
    k_project4<<<blocksC4, T>>>((const float4*)vdif, (const float4*)pa, (float4*)out);
}